// round 5
// baseline (speedup 1.0000x reference)
#include <cuda_runtime.h>
#include <cstdint>

// Problem constants
#define B_ 16
#define L_ 680
#define C_ 1024
#define H_ 16
#define D_ 64
#define M_ (B_ * L_)     // 10880
#define N1_ (3 * C_)     // 3072
#define MAXLOG 4.605170185988091f   // ln(100)

// ---------------- scratch (static __device__, no allocations) ----------------
__device__ float g_qkv[(size_t)M_ * N1_];          // GEMM1 output [M, 3C]
__device__ float g_q[(size_t)B_ * H_ * L_ * D_];   // normalized q, [B,H,L,D]
__device__ float g_k[(size_t)B_ * H_ * L_ * D_];
__device__ float g_v[(size_t)B_ * H_ * L_ * D_];
__device__ float g_att[(size_t)M_ * C_];           // attention out, [M, C]

// ---------------- helpers ----------------
__device__ __forceinline__ unsigned f2tf(float x) {
    unsigned r;
    asm("cvt.rna.tf32.f32 %0, %1;" : "=r"(r) : "f"(x));
    return r;
}

__device__ __forceinline__ void mma_tf32(float c[4], const unsigned a[4],
                                         unsigned b0, unsigned b1) {
    asm volatile(
        "mma.sync.aligned.m16n8k8.row.col.f32.tf32.tf32.f32 "
        "{%0,%1,%2,%3}, {%4,%5,%6,%7}, {%8,%9}, {%0,%1,%2,%3};"
        : "+f"(c[0]), "+f"(c[1]), "+f"(c[2]), "+f"(c[3])
        : "r"(a[0]), "r"(a[1]), "r"(a[2]), "r"(a[3]), "r"(b0), "r"(b1));
}

// packed dual-FMA (Blackwell f32x2). mov.b64 pack/unpack is free (reg pairing).
__device__ __forceinline__ void ffma2(float2 &d, const float2 a, const float2 b) {
    unsigned long long du, au, bu;
    asm("mov.b64 %0, {%1, %2};" : "=l"(au) : "f"(a.x), "f"(a.y));
    asm("mov.b64 %0, {%1, %2};" : "=l"(bu) : "f"(b.x), "f"(b.y));
    asm("mov.b64 %0, {%1, %2};" : "=l"(du) : "f"(d.x), "f"(d.y));
    asm("fma.rn.f32x2 %0, %1, %2, %3;" : "=l"(du) : "l"(au), "l"(bu), "l"(du));
    asm("mov.b64 {%0, %1}, %2;" : "=f"(d.x), "=f"(d.y) : "l"(du));
}

// ---------------- GEMM: C[m,n] = sum_k A[m,k]*W[n,k] + bias(n) ----------------
// mode 0: bias = b0p[n]   (proj)
// mode 1: bias = qkv bias: n<1024 -> b0p[n]; n<2048 -> 0; else b1p[n-2048]
__global__ __launch_bounds__(256, 2)
void gemm_tf32_kernel(const float* __restrict__ A, const float* __restrict__ W,
                      const float* __restrict__ b0p, const float* __restrict__ b1p,
                      float* __restrict__ Cout, int N, int K, int mode)
{
    __shared__ unsigned As[128][36];   // +4 pad -> bank = (4*row + col) & 31
    __shared__ unsigned Bs[128][36];

    const int bm = blockIdx.y * 128, bn = blockIdx.x * 128;
    const int tid  = threadIdx.x;
    const int lane = tid & 31, warp = tid >> 5;
    const int wm = (warp >> 1) * 32;   // 4 warps along m
    const int wn = (warp & 1) * 64;    // 2 warps along n
    const int gid = lane >> 2, tig = lane & 3;
    const int lrow = tid >> 3;         // 0..31
    const int lcol = (tid & 7) * 4;    // 0,4,...,28

    float acc[2][8][4];
    #pragma unroll
    for (int mt = 0; mt < 2; mt++)
        #pragma unroll
        for (int nt = 0; nt < 8; nt++)
            #pragma unroll
            for (int r = 0; r < 4; r++) acc[mt][nt][r] = 0.f;

    const float* Ag = A + (size_t)(bm + lrow) * K;
    const float* Wg = W + (size_t)(bn + lrow) * K;

    for (int kt = 0; kt < K; kt += 32) {
        __syncthreads();
        #pragma unroll
        for (int i = 0; i < 4; i++) {
            float4 av = *(const float4*)(Ag + (size_t)i * 32 * K + kt + lcol);
            float4 bv = *(const float4*)(Wg + (size_t)i * 32 * K + kt + lcol);
            uint4 au = make_uint4(f2tf(av.x), f2tf(av.y), f2tf(av.z), f2tf(av.w));
            uint4 bu = make_uint4(f2tf(bv.x), f2tf(bv.y), f2tf(bv.z), f2tf(bv.w));
            *(uint4*)&As[lrow + i * 32][lcol] = au;
            *(uint4*)&Bs[lrow + i * 32][lcol] = bu;
        }
        __syncthreads();

        #pragma unroll
        for (int ks = 0; ks < 32; ks += 8) {
            unsigned a[2][4];
            #pragma unroll
            for (int mt = 0; mt < 2; mt++) {
                int r = wm + mt * 16 + gid;
                a[mt][0] = As[r][ks + tig];
                a[mt][1] = As[r + 8][ks + tig];
                a[mt][2] = As[r][ks + tig + 4];
                a[mt][3] = As[r + 8][ks + tig + 4];
            }
            #pragma unroll
            for (int nt = 0; nt < 8; nt++) {
                int n = wn + nt * 8 + gid;
                unsigned bb0 = Bs[n][ks + tig];
                unsigned bb1 = Bs[n][ks + tig + 4];
                mma_tf32(acc[0][nt], a[0], bb0, bb1);
                mma_tf32(acc[1][nt], a[1], bb0, bb1);
            }
        }
    }

    #pragma unroll
    for (int mt = 0; mt < 2; mt++) {
        #pragma unroll
        for (int nt = 0; nt < 8; nt++) {
            int row = bm + wm + mt * 16 + gid;
            int col = bn + wn + nt * 8 + 2 * tig;
            float bz0, bz1;
            if (mode == 0) {
                bz0 = b0p[col]; bz1 = b0p[col + 1];
            } else {
                if (col < 1024)       { bz0 = b0p[col];        bz1 = b0p[col + 1]; }
                else if (col < 2048)  { bz0 = 0.f;             bz1 = 0.f; }
                else                  { bz0 = b1p[col - 2048]; bz1 = b1p[col - 2047]; }
            }
            *(float2*)&Cout[(size_t)row * N + col] =
                make_float2(acc[mt][nt][0] + bz0, acc[mt][nt][1] + bz1);
            *(float2*)&Cout[(size_t)(row + 8) * N + col] =
                make_float2(acc[mt][nt][2] + bz0, acc[mt][nt][3] + bz1);
        }
    }
}

// ---------------- l2norm + scale + transpose to [B,H,L,D] ----------------
__global__ __launch_bounds__(256)
void norm_kernel(const float* __restrict__ Y, const float* __restrict__ sl,
                 float* __restrict__ Q, float* __restrict__ Ko, float* __restrict__ V)
{
    int w    = blockIdx.x * 8 + (threadIdx.x >> 5);   // one warp per (m,h)
    int lane = threadIdx.x & 31;
    int m = w >> 4, h = w & 15;
    int b = m / L_, l = m % L_;

    const float* row = Y + (size_t)m * N1_ + h * 64 + lane * 2;
    float2 qv = *(const float2*)(row);
    float2 kv = *(const float2*)(row + 1024);
    float2 vv = *(const float2*)(row + 2048);

    float ssq = qv.x * qv.x + qv.y * qv.y;
    float ssk = kv.x * kv.x + kv.y * kv.y;
    #pragma unroll
    for (int o = 16; o; o >>= 1) {
        ssq += __shfl_xor_sync(0xffffffffu, ssq, o);
        ssk += __shfl_xor_sync(0xffffffffu, ssk, o);
    }
    float qs = expf(fminf(sl[h], MAXLOG)) / fmaxf(sqrtf(ssq), 1e-12f);
    float ks = 1.0f / fmaxf(sqrtf(ssk), 1e-12f);

    size_t ob = ((size_t)(b * H_ + h) * L_ + l) * 64 + lane * 2;
    *(float2*)(Q  + ob) = make_float2(qv.x * qs, qv.y * qs);
    *(float2*)(Ko + ob) = make_float2(kv.x * ks, kv.y * ks);
    *(float2*)(V  + ob) = vv;
}

// ---------------- block-diagonal attention ----------------
// one CTA per (segment, head, batch); thread i = query row i.
// |q| = scale, |k| = 1  =>  s <= scale: fixed softmax max, no rescale pass.
__global__ __launch_bounds__(256)
void attn_kernel(const float* __restrict__ Q, const float* __restrict__ Kn,
                 const float* __restrict__ V, const float* __restrict__ sl,
                 float* __restrict__ Att)
{
    extern __shared__ float smdyn[];
    const int seg = blockIdx.x, h = blockIdx.y, b = blockIdx.z;
    const int pn[10]  = {1, 4, 9, 16, 25, 36, 64, 100, 169, 256};
    const int off[10] = {0, 1, 5, 14, 30, 55, 91, 155, 255, 424};
    const int ln = pn[seg], start = off[seg];

    float* Ks = smdyn;
    float* Vs = smdyn + ln * 64;
    const int tid = threadIdx.x;
    const size_t base = ((size_t)(b * H_ + h) * L_ + start) * 64;

    for (int idx = tid * 4; idx < ln * 64; idx += 1024) {
        *(float4*)&Ks[idx] = *(const float4*)&Kn[base + idx];
        *(float4*)&Vs[idx] = *(const float4*)&V[base + idx];
    }
    const float mfix = expf(fminf(sl[h], MAXLOG));
    __syncthreads();

    float2 of[32];
    float lsum = 0.f;
    if (tid < ln) {
        float2 qf[32];
        #pragma unroll
        for (int t = 0; t < 16; t++) {
            float4 qv = *(const float4*)&Q[base + (size_t)tid * 64 + t * 4];
            qf[2 * t]     = make_float2(qv.x, qv.y);
            qf[2 * t + 1] = make_float2(qv.z, qv.w);
        }
        #pragma unroll
        for (int t = 0; t < 32; t++) of[t] = make_float2(0.f, 0.f);

        for (int j = 0; j < ln; j++) {
            const float4* kp = (const float4*)(Ks + j * 64);
            float2 aA[4], aB[4];
            #pragma unroll
            for (int t = 0; t < 4; t++) {
                aA[t] = make_float2(0.f, 0.f);
                aB[t] = make_float2(0.f, 0.f);
            }
            #pragma unroll
            for (int t = 0; t < 16; t++) {
                float4 kvv = kp[t];
                ffma2(aA[t & 3], qf[2 * t],     make_float2(kvv.x, kvv.y));
                ffma2(aB[t & 3], qf[2 * t + 1], make_float2(kvv.z, kvv.w));
            }
            float2 r = make_float2(aA[0].x + aA[1].x + aA[2].x + aA[3].x +
                                   aB[0].x + aB[1].x + aB[2].x + aB[3].x,
                                   aA[0].y + aA[1].y + aA[2].y + aA[3].y +
                                   aB[0].y + aB[1].y + aB[2].y + aB[3].y);
            float s = r.x + r.y;
            float p = __expf(s - mfix);
            lsum += p;
            float2 pp = make_float2(p, p);
            const float4* vp = (const float4*)(Vs + j * 64);
            #pragma unroll
            for (int t = 0; t < 16; t++) {
                float4 vvv = vp[t];
                ffma2(of[2 * t],     pp, make_float2(vvv.x, vvv.y));
                ffma2(of[2 * t + 1], pp, make_float2(vvv.z, vvv.w));
            }
        }
    }
    __syncthreads();              // done reading Ks -> reuse as output stage
    if (tid < ln) {
        float inv = 1.0f / lsum;
        #pragma unroll
        for (int t = 0; t < 32; t++) {
            Ks[tid * 64 + 2 * t]     = of[t].x * inv;
            Ks[tid * 64 + 2 * t + 1] = of[t].y * inv;
        }
    }
    __syncthreads();
    const size_t ob = (size_t)(b * L_ + start);
    for (int idx = tid * 4; idx < ln * 64; idx += 1024) {
        int row = idx >> 6, e = idx & 63;
        *(float4*)&Att[(ob + row) * C_ + h * 64 + e] = *(float4*)&Ks[idx];
    }
}

// ---------------- launch ----------------
extern "C" void kernel_launch(void* const* d_in, const int* in_sizes, int n_in,
                              void* d_out, int out_size)
{
    const float* x    = (const float*)d_in[0];
    // d_in[1] = patch_nums (fixed for this problem; offsets compiled in)
    const float* wqkv = (const float*)d_in[2];
    const float* qb   = (const float*)d_in[3];
    const float* vb   = (const float*)d_in[4];
    const float* slog = (const float*)d_in[5];
    const float* wp   = (const float*)d_in[6];
    const float* pb   = (const float*)d_in[7];
    float* out = (float*)d_out;

    float *qkv, *q, *k, *v, *att;
    cudaGetSymbolAddress((void**)&qkv, g_qkv);
    cudaGetSymbolAddress((void**)&q,   g_q);
    cudaGetSymbolAddress((void**)&k,   g_k);
    cudaGetSymbolAddress((void**)&v,   g_v);
    cudaGetSymbolAddress((void**)&att, g_att);

    // attention needs 2 * 256 * 64 * 4 = 128 KB dynamic smem for the largest segment
    cudaFuncSetAttribute(attn_kernel,
                         cudaFuncAttributeMaxDynamicSharedMemorySize, 131072);

    // 1) QKV projection (tf32 tensor cores), fused bias
    gemm_tf32_kernel<<<dim3(N1_ / 128, M_ / 128), 256>>>(
        x, wqkv, qb, vb, qkv, N1_, C_, 1);

    // 2) l2norm q/k + per-head scale + transpose to [B,H,L,D]
    norm_kernel<<<(M_ * H_) / 8, 256>>>(qkv, slog, q, k, v);

    // 3) block-diagonal attention, one CTA per (seg, head, batch)
    attn_kernel<<<dim3(10, H_, B_), 256, 131072>>>(q, k, v, slog, att);

    // 4) output projection (tf32 tensor cores), fused bias -> d_out
    gemm_tf32_kernel<<<dim3(C_ / 128, M_ / 128), 256>>>(
        att, wp, pb, nullptr, out, C_, C_, 0);
}

// round 9
// speedup vs baseline: 1.0883x; 1.0883x over previous
#include <cuda_runtime.h>
#include <cstdint>

// Problem constants
#define B_ 16
#define L_ 680
#define C_ 1024
#define H_ 16
#define D_ 64
#define M_ (B_ * L_)     // 10880
#define N1_ (3 * C_)     // 3072
#define MAXLOG 4.605170185988091f   // ln(100)

// ---------------- scratch (static __device__, no allocations) ----------------
__device__ float g_qkv[(size_t)M_ * N1_];          // GEMM1 output [M, 3C]
__device__ float g_q[(size_t)B_ * H_ * L_ * D_];   // normalized q, [B,H,L,D]
__device__ float g_k[(size_t)B_ * H_ * L_ * D_];
__device__ float g_v[(size_t)B_ * H_ * L_ * D_];
__device__ float g_att[(size_t)M_ * C_];           // attention out, [M, C]

// ---------------- helpers ----------------
__device__ __forceinline__ unsigned f2tf(float x) {
    unsigned r;
    asm("cvt.rna.tf32.f32 %0, %1;" : "=r"(r) : "f"(x));
    return r;
}

__device__ __forceinline__ void mma_tf32(float c[4], const unsigned a[4],
                                         unsigned b0, unsigned b1) {
    asm volatile(
        "mma.sync.aligned.m16n8k8.row.col.f32.tf32.tf32.f32 "
        "{%0,%1,%2,%3}, {%4,%5,%6,%7}, {%8,%9}, {%0,%1,%2,%3};"
        : "+f"(c[0]), "+f"(c[1]), "+f"(c[2]), "+f"(c[3])
        : "r"(a[0]), "r"(a[1]), "r"(a[2]), "r"(a[3]), "r"(b0), "r"(b1));
}

__device__ __forceinline__ void cp16(float* s, const float* g) {
    unsigned sa = (unsigned)__cvta_generic_to_shared(s);
    asm volatile("cp.async.cg.shared.global [%0], [%1], 16;" :: "r"(sa), "l"(g));
}
__device__ __forceinline__ void cp_commit() {
    asm volatile("cp.async.commit_group;");
}
template<int N> __device__ __forceinline__ void cp_wait() {
    asm volatile("cp.async.wait_group %0;" :: "n"(N));
}

// packed f32x2 primitives — operands STAY packed across the loop (no movs inside)
typedef unsigned long long u64;
__device__ __forceinline__ void pfma(u64& d, u64 a, u64 b) {
    asm("fma.rn.f32x2 %0, %1, %2, %0;" : "+l"(d) : "l"(a), "l"(b));
}
__device__ __forceinline__ float2 up2(u64 v) {
    float2 r; asm("mov.b64 {%0, %1}, %2;" : "=f"(r.x), "=f"(r.y) : "l"(v)); return r;
}
__device__ __forceinline__ u64 pk2(float x, float y) {
    u64 r; asm("mov.b64 %0, {%1, %2};" : "=l"(r) : "f"(x), "f"(y)); return r;
}

// ---------------- GEMM: C[m,n] = sum_k A[m,k]*W[n,k] + bias(n) ----------------
// cp.async 2-stage pipeline; raw fp32 in smem; cvt to tf32 at fragment load.
// mode 0: bias = b0p[n]   (proj)
// mode 1: qkv bias: n<1024 -> b0p[n]; n<2048 -> 0; else b1p[n-2048]
#define SROW 36                       // +4 pad: fragment LDS conflict-free
#define STAGEF (2 * 128 * SROW)       // floats per stage (A then B)

__global__ __launch_bounds__(256, 2)
void gemm_tf32_kernel(const float* __restrict__ A, const float* __restrict__ W,
                      const float* __restrict__ b0p, const float* __restrict__ b1p,
                      float* __restrict__ Cout, int N, int K, int mode)
{
    extern __shared__ float sm[];

    const int bm = blockIdx.y * 128, bn = blockIdx.x * 128;
    const int tid  = threadIdx.x;
    const int lane = tid & 31, warp = tid >> 5;
    const int wm = (warp >> 1) * 32;   // 4 warps along m
    const int wn = (warp & 1) * 64;    // 2 warps along n
    const int gid = lane >> 2, tig = lane & 3;
    const int lrow = tid >> 3;         // 0..31
    const int lcol = (tid & 7) * 4;    // 0,4,...,28

    float acc[2][8][4];
    #pragma unroll
    for (int mt = 0; mt < 2; mt++)
        #pragma unroll
        for (int nt = 0; nt < 8; nt++)
            #pragma unroll
            for (int r = 0; r < 4; r++) acc[mt][nt][r] = 0.f;

    const float* Ag = A + (size_t)(bm + lrow) * K + lcol;
    const float* Wg = W + (size_t)(bn + lrow) * K + lcol;

    const int NCH = K >> 5;            // 32-wide k chunks

    // prologue: prefetch chunk 0 into stage 0
    {
        float* sA = sm;
        float* sB = sm + 128 * SROW;
        #pragma unroll
        for (int i = 0; i < 4; i++) {
            cp16(&sA[(lrow + i * 32) * SROW + lcol], Ag + (size_t)i * 32 * K);
            cp16(&sB[(lrow + i * 32) * SROW + lcol], Wg + (size_t)i * 32 * K);
        }
        cp_commit();
    }

    for (int it = 0; it < NCH; it++) {
        if (it + 1 < NCH) {
            // prefetch next chunk into the other stage, then wait for current
            float* sA = sm + ((it + 1) & 1) * STAGEF;
            float* sB = sA + 128 * SROW;
            const float* Ap = Ag + (size_t)(it + 1) * 32;
            const float* Wp = Wg + (size_t)(it + 1) * 32;
            #pragma unroll
            for (int i = 0; i < 4; i++) {
                cp16(&sA[(lrow + i * 32) * SROW + lcol], Ap + (size_t)i * 32 * K);
                cp16(&sB[(lrow + i * 32) * SROW + lcol], Wp + (size_t)i * 32 * K);
            }
            cp_commit();
            cp_wait<1>();
        } else {
            cp_wait<0>();
        }
        __syncthreads();

        const float* sA = sm + (it & 1) * STAGEF;
        const float* sB = sA + 128 * SROW;

        #pragma unroll
        for (int ks = 0; ks < 32; ks += 8) {
            unsigned a[2][4];
            #pragma unroll
            for (int mt = 0; mt < 2; mt++) {
                int r = wm + mt * 16 + gid;
                a[mt][0] = f2tf(sA[r * SROW + ks + tig]);
                a[mt][1] = f2tf(sA[(r + 8) * SROW + ks + tig]);
                a[mt][2] = f2tf(sA[r * SROW + ks + tig + 4]);
                a[mt][3] = f2tf(sA[(r + 8) * SROW + ks + tig + 4]);
            }
            #pragma unroll
            for (int nt = 0; nt < 8; nt++) {
                int n = wn + nt * 8 + gid;
                unsigned bb0 = f2tf(sB[n * SROW + ks + tig]);
                unsigned bb1 = f2tf(sB[n * SROW + ks + tig + 4]);
                mma_tf32(acc[0][nt], a[0], bb0, bb1);
                mma_tf32(acc[1][nt], a[1], bb0, bb1);
            }
        }
        __syncthreads();   // stage (it&1) free for the prefetch two iters ahead
    }

    #pragma unroll
    for (int mt = 0; mt < 2; mt++) {
        #pragma unroll
        for (int nt = 0; nt < 8; nt++) {
            int row = bm + wm + mt * 16 + gid;
            int col = bn + wn + nt * 8 + 2 * tig;
            float bz0, bz1;
            if (mode == 0) {
                bz0 = b0p[col]; bz1 = b0p[col + 1];
            } else {
                if (col < 1024)       { bz0 = b0p[col];        bz1 = b0p[col + 1]; }
                else if (col < 2048)  { bz0 = 0.f;             bz1 = 0.f; }
                else                  { bz0 = b1p[col - 2048]; bz1 = b1p[col - 2047]; }
            }
            *(float2*)&Cout[(size_t)row * N + col] =
                make_float2(acc[mt][nt][0] + bz0, acc[mt][nt][1] + bz1);
            *(float2*)&Cout[(size_t)(row + 8) * N + col] =
                make_float2(acc[mt][nt][2] + bz0, acc[mt][nt][3] + bz1);
        }
    }
}

// ---------------- l2norm + scale + transpose to [B,H,L,D] ----------------
__global__ __launch_bounds__(256)
void norm_kernel(const float* __restrict__ Y, const float* __restrict__ sl,
                 float* __restrict__ Q, float* __restrict__ Ko, float* __restrict__ V)
{
    int w    = blockIdx.x * 8 + (threadIdx.x >> 5);   // one warp per (m,h)
    int lane = threadIdx.x & 31;
    int m = w >> 4, h = w & 15;
    int b = m / L_, l = m % L_;

    const float* row = Y + (size_t)m * N1_ + h * 64 + lane * 2;
    float2 qv = *(const float2*)(row);
    float2 kv = *(const float2*)(row + 1024);
    float2 vv = *(const float2*)(row + 2048);

    float ssq = qv.x * qv.x + qv.y * qv.y;
    float ssk = kv.x * kv.x + kv.y * kv.y;
    #pragma unroll
    for (int o = 16; o; o >>= 1) {
        ssq += __shfl_xor_sync(0xffffffffu, ssq, o);
        ssk += __shfl_xor_sync(0xffffffffu, ssk, o);
    }
    float qs = expf(fminf(sl[h], MAXLOG)) / fmaxf(sqrtf(ssq), 1e-12f);
    float ks = 1.0f / fmaxf(sqrtf(ssk), 1e-12f);

    size_t ob = ((size_t)(b * H_ + h) * L_ + l) * 64 + lane * 2;
    *(float2*)(Q  + ob) = make_float2(qv.x * qs, qv.y * qs);
    *(float2*)(Ko + ob) = make_float2(kv.x * ks, kv.y * ks);
    *(float2*)(V  + ob) = vv;
}

// ---------------- block-diagonal attention ----------------
// 1-D grid, 2560 CTAs; biggest segments scheduled FIRST (cta 0..255 = seg 9).
// thread i = query row i. |q| = scale, |k| = 1 => s <= scale: fixed softmax max.
// All operands stay packed f32x2 (u64) through the whole j-loop — no mov traffic.
__global__ __launch_bounds__(256)
void attn_kernel(const float* __restrict__ Q, const float* __restrict__ Kn,
                 const float* __restrict__ V, const float* __restrict__ sl,
                 float* __restrict__ Att)
{
    extern __shared__ float smdyn[];
    const int cta = blockIdx.x;
    const int seg = 9 - (cta >> 8);          // big segs first
    const int hb  = cta & 255;
    const int h = hb & 15, b = hb >> 4;

    const int pn[10]  = {1, 4, 9, 16, 25, 36, 64, 100, 169, 256};
    const int off[10] = {0, 1, 5, 14, 30, 55, 91, 155, 255, 424};
    const int ln = pn[seg], start = off[seg];

    float* Ks = smdyn;
    float* Vs = smdyn + ln * 64;
    const int tid = threadIdx.x;
    const size_t base = ((size_t)(b * H_ + h) * L_ + start) * 64;

    for (int idx = tid * 4; idx < ln * 64; idx += 1024) {
        *(float4*)&Ks[idx] = *(const float4*)&Kn[base + idx];
        *(float4*)&Vs[idx] = *(const float4*)&V[base + idx];
    }
    const float mfix = expf(fminf(sl[h], MAXLOG));
    __syncthreads();

    u64 op[32];
    float lsum = 0.f;
    if (tid < ln) {
        u64 qp[32];
        const u64* qg = (const u64*)(Q + base + (size_t)tid * 64);
        #pragma unroll
        for (int t = 0; t < 32; t++) { qp[t] = qg[t]; op[t] = 0ull; }

        for (int j = 0; j < ln; j++) {
            const u64* kp = (const u64*)(Ks + j * 64);
            u64 s8[8];
            #pragma unroll
            for (int t = 0; t < 8; t++) s8[t] = 0ull;
            #pragma unroll
            for (int t = 0; t < 32; t++) pfma(s8[t & 7], qp[t], kp[t]);

            float tot = 0.f;
            #pragma unroll
            for (int r = 0; r < 8; r++) { float2 f = up2(s8[r]); tot += f.x + f.y; }

            float p = __expf(tot - mfix);
            lsum += p;
            u64 pp = pk2(p, p);

            const u64* vp = (const u64*)(Vs + j * 64);
            #pragma unroll
            for (int t = 0; t < 32; t++) pfma(op[t], pp, vp[t]);
        }
    }
    __syncthreads();              // done reading Ks -> reuse as output stage
    if (tid < ln) {
        float inv = 1.0f / lsum;
        #pragma unroll
        for (int t = 0; t < 32; t++) {
            float2 f = up2(op[t]);
            Ks[tid * 64 + 2 * t]     = f.x * inv;
            Ks[tid * 64 + 2 * t + 1] = f.y * inv;
        }
    }
    __syncthreads();
    const size_t ob = (size_t)(b * L_ + start);
    for (int idx = tid * 4; idx < ln * 64; idx += 1024) {
        int row = idx >> 6, e = idx & 63;
        *(float4*)&Att[(ob + row) * C_ + h * 64 + e] = *(float4*)&Ks[idx];
    }
}

// ---------------- launch ----------------
extern "C" void kernel_launch(void* const* d_in, const int* in_sizes, int n_in,
                              void* d_out, int out_size)
{
    const float* x    = (const float*)d_in[0];
    // d_in[1] = patch_nums (fixed for this problem; offsets compiled in)
    const float* wqkv = (const float*)d_in[2];
    const float* qb   = (const float*)d_in[3];
    const float* vb   = (const float*)d_in[4];
    const float* slog = (const float*)d_in[5];
    const float* wp   = (const float*)d_in[6];
    const float* pb   = (const float*)d_in[7];
    float* out = (float*)d_out;

    float *qkv, *q, *k, *v, *att;
    cudaGetSymbolAddress((void**)&qkv, g_qkv);
    cudaGetSymbolAddress((void**)&q,   g_q);
    cudaGetSymbolAddress((void**)&k,   g_k);
    cudaGetSymbolAddress((void**)&v,   g_v);
    cudaGetSymbolAddress((void**)&att, g_att);

    const int gemm_smem = STAGEF * 2 * (int)sizeof(float);   // 73728 B
    cudaFuncSetAttribute(gemm_tf32_kernel,
                         cudaFuncAttributeMaxDynamicSharedMemorySize, gemm_smem);
    cudaFuncSetAttribute(attn_kernel,
                         cudaFuncAttributeMaxDynamicSharedMemorySize, 131072);

    // 1) QKV projection (tf32 tensor cores, cp.async pipelined), fused bias
    gemm_tf32_kernel<<<dim3(N1_ / 128, M_ / 128), 256, gemm_smem>>>(
        x, wqkv, qb, vb, qkv, N1_, C_, 1);

    // 2) l2norm q/k + per-head scale + transpose to [B,H,L,D]
    norm_kernel<<<(M_ * H_) / 8, 256>>>(qkv, slog, q, k, v);

    // 3) block-diagonal attention, big segments first
    attn_kernel<<<2560, 256, 131072>>>(q, k, v, slog, att);

    // 4) output projection (tf32 tensor cores, cp.async pipelined) -> d_out
    gemm_tf32_kernel<<<dim3(C_ / 128, M_ / 128), 256, gemm_smem>>>(
        att, wp, pb, nullptr, out, C_, C_, 0);
}

// round 10
// speedup vs baseline: 1.1032x; 1.0137x over previous
#include <cuda_runtime.h>
#include <cstdint>

// Problem constants
#define B_ 16
#define L_ 680
#define C_ 1024
#define H_ 16
#define D_ 64
#define M_ (B_ * L_)     // 10880
#define N1_ (3 * C_)     // 3072
#define MAXLOG 4.605170185988091f   // ln(100)

// ---------------- scratch (static __device__, no allocations) ----------------
__device__ float g_qkv[(size_t)M_ * N1_];          // GEMM1 output [M, 3C]
__device__ float g_q[(size_t)B_ * H_ * L_ * D_];   // normalized q, [B,H,L,D]
__device__ float g_k[(size_t)B_ * H_ * L_ * D_];
__device__ float g_v[(size_t)B_ * H_ * L_ * D_];
__device__ float g_att[(size_t)M_ * C_];           // attention out (tf32-rounded), [M, C]
__device__ float g_xr[(size_t)M_ * C_];            // x rounded to tf32
__device__ float g_wqkvr[(size_t)N1_ * C_];        // wqkv rounded to tf32
__device__ float g_wpr[(size_t)C_ * C_];           // wp rounded to tf32

// ---------------- helpers ----------------
__device__ __forceinline__ unsigned f2tf(float x) {
    unsigned r;
    asm("cvt.rna.tf32.f32 %0, %1;" : "=r"(r) : "f"(x));
    return r;
}

__device__ __forceinline__ void mma_tf32(float c[4], const unsigned a[4],
                                         unsigned b0, unsigned b1) {
    asm volatile(
        "mma.sync.aligned.m16n8k8.row.col.f32.tf32.tf32.f32 "
        "{%0,%1,%2,%3}, {%4,%5,%6,%7}, {%8,%9}, {%0,%1,%2,%3};"
        : "+f"(c[0]), "+f"(c[1]), "+f"(c[2]), "+f"(c[3])
        : "r"(a[0]), "r"(a[1]), "r"(a[2]), "r"(a[3]), "r"(b0), "r"(b1));
}

__device__ __forceinline__ void cp16(unsigned* s, const float* g) {
    unsigned sa = (unsigned)__cvta_generic_to_shared(s);
    asm volatile("cp.async.cg.shared.global [%0], [%1], 16;" :: "r"(sa), "l"(g));
}
__device__ __forceinline__ void cp_commit() {
    asm volatile("cp.async.commit_group;");
}
template<int N> __device__ __forceinline__ void cp_wait() {
    asm volatile("cp.async.wait_group %0;" :: "n"(N));
}

// packed f32x2 primitives — operands STAY packed across the loop (no movs inside)
typedef unsigned long long u64;
__device__ __forceinline__ void pfma(u64& d, u64 a, u64 b) {
    asm("fma.rn.f32x2 %0, %1, %2, %0;" : "+l"(d) : "l"(a), "l"(b));
}
__device__ __forceinline__ float2 up2(u64 v) {
    float2 r; asm("mov.b64 {%0, %1}, %2;" : "=f"(r.x), "=f"(r.y) : "l"(v)); return r;
}
__device__ __forceinline__ u64 pk2(float x, float y) {
    u64 r; asm("mov.b64 %0, {%1, %2};" : "=l"(r) : "f"(x), "f"(y)); return r;
}

// ---------------- tf32 pre-round (elementwise) ----------------
__global__ __launch_bounds__(256)
void round_tf32_kernel(const float* __restrict__ src, float* __restrict__ dst, int n)
{
    int i = (blockIdx.x * 256 + threadIdx.x) * 4;
    if (i < n) {
        float4 v = *(const float4*)(src + i);
        uint4 r = make_uint4(f2tf(v.x), f2tf(v.y), f2tf(v.z), f2tf(v.w));
        *(uint4*)(dst + i) = r;
    }
}

// ---------------- GEMM: C[m,n] = sum_k A[m,k]*W[n,k] + bias(n) ----------------
// Inputs are PRE-ROUNDED tf32 bit patterns; smem holds them raw; no cvt in loop.
// 128 threads (4 warps), CTA tile 128x128, warp tile 64x64 (mt=4, nt=8).
// mode 0: bias = b0p[n]   (proj)
// mode 1: qkv bias: n<1024 -> b0p[n]; n<2048 -> 0; else b1p[n-2048]
#define SROW 36                       // +4 pad: fragment LDS conflict-free
#define STAGEF (2 * 128 * SROW)       // words per stage (A then B)

__global__ __launch_bounds__(128, 2)
void gemm_tf32_kernel(const float* __restrict__ A, const float* __restrict__ W,
                      const float* __restrict__ b0p, const float* __restrict__ b1p,
                      float* __restrict__ Cout, int N, int K, int mode)
{
    extern __shared__ unsigned sm[];

    const int bm = blockIdx.y * 128, bn = blockIdx.x * 128;
    const int tid  = threadIdx.x;
    const int lane = tid & 31, warp = tid >> 5;
    const int wm = (warp >> 1) * 64;   // 2 warps along m
    const int wn = (warp & 1) * 64;    // 2 warps along n
    const int gid = lane >> 2, tig = lane & 3;
    const int lrow = tid >> 3;         // 0..15
    const int lcol = (tid & 7) * 4;    // 0,4,...,28

    float acc[4][8][4];
    #pragma unroll
    for (int mt = 0; mt < 4; mt++)
        #pragma unroll
        for (int nt = 0; nt < 8; nt++)
            #pragma unroll
            for (int r = 0; r < 4; r++) acc[mt][nt][r] = 0.f;

    const float* Ag = A + (size_t)(bm + lrow) * K + lcol;
    const float* Wg = W + (size_t)(bn + lrow) * K + lcol;

    const int NCH = K >> 5;            // 32-wide k chunks

    // prologue: prefetch chunk 0 into stage 0
    {
        unsigned* sA = sm;
        unsigned* sB = sm + 128 * SROW;
        #pragma unroll
        for (int i = 0; i < 8; i++) {
            cp16(&sA[(lrow + i * 16) * SROW + lcol], Ag + (size_t)i * 16 * K);
            cp16(&sB[(lrow + i * 16) * SROW + lcol], Wg + (size_t)i * 16 * K);
        }
        cp_commit();
    }

    for (int it = 0; it < NCH; it++) {
        if (it + 1 < NCH) {
            unsigned* sA = sm + ((it + 1) & 1) * STAGEF;
            unsigned* sB = sA + 128 * SROW;
            const float* Ap = Ag + (size_t)(it + 1) * 32;
            const float* Wp = Wg + (size_t)(it + 1) * 32;
            #pragma unroll
            for (int i = 0; i < 8; i++) {
                cp16(&sA[(lrow + i * 16) * SROW + lcol], Ap + (size_t)i * 16 * K);
                cp16(&sB[(lrow + i * 16) * SROW + lcol], Wp + (size_t)i * 16 * K);
            }
            cp_commit();
            cp_wait<1>();
        } else {
            cp_wait<0>();
        }
        __syncthreads();

        const unsigned* sA = sm + (it & 1) * STAGEF;
        const unsigned* sB = sA + 128 * SROW;

        #pragma unroll
        for (int ks = 0; ks < 32; ks += 8) {
            unsigned a[4][4];
            #pragma unroll
            for (int mt = 0; mt < 4; mt++) {
                int r = wm + mt * 16 + gid;
                a[mt][0] = sA[r * SROW + ks + tig];
                a[mt][1] = sA[(r + 8) * SROW + ks + tig];
                a[mt][2] = sA[r * SROW + ks + tig + 4];
                a[mt][3] = sA[(r + 8) * SROW + ks + tig + 4];
            }
            #pragma unroll
            for (int nt = 0; nt < 8; nt++) {
                int n = wn + nt * 8 + gid;
                unsigned bb0 = sB[n * SROW + ks + tig];
                unsigned bb1 = sB[n * SROW + ks + tig + 4];
                #pragma unroll
                for (int mt = 0; mt < 4; mt++)
                    mma_tf32(acc[mt][nt], a[mt], bb0, bb1);
            }
        }
        __syncthreads();   // stage free for the prefetch two iters ahead
    }

    #pragma unroll
    for (int mt = 0; mt < 4; mt++) {
        #pragma unroll
        for (int nt = 0; nt < 8; nt++) {
            int row = bm + wm + mt * 16 + gid;
            int col = bn + wn + nt * 8 + 2 * tig;
            float bz0, bz1;
            if (mode == 0) {
                bz0 = b0p[col]; bz1 = b0p[col + 1];
            } else {
                if (col < 1024)       { bz0 = b0p[col];        bz1 = b0p[col + 1]; }
                else if (col < 2048)  { bz0 = 0.f;             bz1 = 0.f; }
                else                  { bz0 = b1p[col - 2048]; bz1 = b1p[col - 2047]; }
            }
            *(float2*)&Cout[(size_t)row * N + col] =
                make_float2(acc[mt][nt][0] + bz0, acc[mt][nt][1] + bz1);
            *(float2*)&Cout[(size_t)(row + 8) * N + col] =
                make_float2(acc[mt][nt][2] + bz0, acc[mt][nt][3] + bz1);
        }
    }
}

// ---------------- l2norm + scale + transpose to [B,H,L,D] ----------------
__global__ __launch_bounds__(256)
void norm_kernel(const float* __restrict__ Y, const float* __restrict__ sl,
                 float* __restrict__ Q, float* __restrict__ Ko, float* __restrict__ V)
{
    int w    = blockIdx.x * 8 + (threadIdx.x >> 5);   // one warp per (m,h)
    int lane = threadIdx.x & 31;
    int m = w >> 4, h = w & 15;
    int b = m / L_, l = m % L_;

    const float* row = Y + (size_t)m * N1_ + h * 64 + lane * 2;
    float2 qv = *(const float2*)(row);
    float2 kv = *(const float2*)(row + 1024);
    float2 vv = *(const float2*)(row + 2048);

    float ssq = qv.x * qv.x + qv.y * qv.y;
    float ssk = kv.x * kv.x + kv.y * kv.y;
    #pragma unroll
    for (int o = 16; o; o >>= 1) {
        ssq += __shfl_xor_sync(0xffffffffu, ssq, o);
        ssk += __shfl_xor_sync(0xffffffffu, ssk, o);
    }
    float qs = expf(fminf(sl[h], MAXLOG)) / fmaxf(sqrtf(ssq), 1e-12f);
    float ks = 1.0f / fmaxf(sqrtf(ssk), 1e-12f);

    size_t ob = ((size_t)(b * H_ + h) * L_ + l) * 64 + lane * 2;
    *(float2*)(Q  + ob) = make_float2(qv.x * qs, qv.y * qs);
    *(float2*)(Ko + ob) = make_float2(kv.x * ks, kv.y * ks);
    *(float2*)(V  + ob) = vv;
}

// ---------------- block-diagonal attention ----------------
// 1-D grid, 2560 CTAs; biggest segments scheduled FIRST (cta 0..255 = seg 9).
// thread i = query row i. |q| = scale, |k| = 1 => s <= scale: fixed softmax max.
// Output is rounded to tf32 at store (feeds the proj GEMM directly).
__global__ __launch_bounds__(256)
void attn_kernel(const float* __restrict__ Q, const float* __restrict__ Kn,
                 const float* __restrict__ V, const float* __restrict__ sl,
                 float* __restrict__ Att)
{
    extern __shared__ float smdyn[];
    const int cta = blockIdx.x;
    const int seg = 9 - (cta >> 8);          // big segs first
    const int hb  = cta & 255;
    const int h = hb & 15, b = hb >> 4;

    const int pn[10]  = {1, 4, 9, 16, 25, 36, 64, 100, 169, 256};
    const int off[10] = {0, 1, 5, 14, 30, 55, 91, 155, 255, 424};
    const int ln = pn[seg], start = off[seg];

    float* Ks = smdyn;
    float* Vs = smdyn + ln * 64;
    const int tid = threadIdx.x;
    const size_t base = ((size_t)(b * H_ + h) * L_ + start) * 64;

    for (int idx = tid * 4; idx < ln * 64; idx += 1024) {
        *(float4*)&Ks[idx] = *(const float4*)&Kn[base + idx];
        *(float4*)&Vs[idx] = *(const float4*)&V[base + idx];
    }
    const float mfix = expf(fminf(sl[h], MAXLOG));
    __syncthreads();

    u64 op[32];
    float lsum = 0.f;
    if (tid < ln) {
        u64 qp[32];
        const u64* qg = (const u64*)(Q + base + (size_t)tid * 64);
        #pragma unroll
        for (int t = 0; t < 32; t++) { qp[t] = qg[t]; op[t] = 0ull; }

        for (int j = 0; j < ln; j++) {
            const u64* kp = (const u64*)(Ks + j * 64);
            u64 s8[8];
            #pragma unroll
            for (int t = 0; t < 8; t++) s8[t] = 0ull;
            #pragma unroll
            for (int t = 0; t < 32; t++) pfma(s8[t & 7], qp[t], kp[t]);

            float tot = 0.f;
            #pragma unroll
            for (int r = 0; r < 8; r++) { float2 f = up2(s8[r]); tot += f.x + f.y; }

            float p = __expf(tot - mfix);
            lsum += p;
            u64 pp = pk2(p, p);

            const u64* vp = (const u64*)(Vs + j * 64);
            #pragma unroll
            for (int t = 0; t < 32; t++) pfma(op[t], pp, vp[t]);
        }
    }
    __syncthreads();              // done reading Ks -> reuse as output stage
    if (tid < ln) {
        float inv = 1.0f / lsum;
        #pragma unroll
        for (int t = 0; t < 32; t++) {
            float2 f = up2(op[t]);
            // round to tf32 here: proj GEMM consumes raw bits with no cvt
            ((unsigned*)Ks)[tid * 64 + 2 * t]     = f2tf(f.x * inv);
            ((unsigned*)Ks)[tid * 64 + 2 * t + 1] = f2tf(f.y * inv);
        }
    }
    __syncthreads();
    const size_t ob = (size_t)(b * L_ + start);
    for (int idx = tid * 4; idx < ln * 64; idx += 1024) {
        int row = idx >> 6, e = idx & 63;
        *(float4*)&Att[(ob + row) * C_ + h * 64 + e] = *(float4*)&Ks[idx];
    }
}

// ---------------- launch ----------------
extern "C" void kernel_launch(void* const* d_in, const int* in_sizes, int n_in,
                              void* d_out, int out_size)
{
    const float* x    = (const float*)d_in[0];
    // d_in[1] = patch_nums (fixed for this problem; offsets compiled in)
    const float* wqkv = (const float*)d_in[2];
    const float* qb   = (const float*)d_in[3];
    const float* vb   = (const float*)d_in[4];
    const float* slog = (const float*)d_in[5];
    const float* wp   = (const float*)d_in[6];
    const float* pb   = (const float*)d_in[7];
    float* out = (float*)d_out;

    float *qkv, *q, *k, *v, *att, *xr, *wqkvr, *wpr;
    cudaGetSymbolAddress((void**)&qkv,   g_qkv);
    cudaGetSymbolAddress((void**)&q,     g_q);
    cudaGetSymbolAddress((void**)&k,     g_k);
    cudaGetSymbolAddress((void**)&v,     g_v);
    cudaGetSymbolAddress((void**)&att,   g_att);
    cudaGetSymbolAddress((void**)&xr,    g_xr);
    cudaGetSymbolAddress((void**)&wqkvr, g_wqkvr);
    cudaGetSymbolAddress((void**)&wpr,   g_wpr);

    const int gemm_smem = STAGEF * 2 * (int)sizeof(unsigned);   // 73728 B
    cudaFuncSetAttribute(gemm_tf32_kernel,
                         cudaFuncAttributeMaxDynamicSharedMemorySize, gemm_smem);
    cudaFuncSetAttribute(attn_kernel,
                         cudaFuncAttributeMaxDynamicSharedMemorySize, 131072);

    // 0) pre-round GEMM operands to tf32 (removes all cvt from GEMM hot loops)
    {
        const int nx = M_ * C_, nw1 = N1_ * C_, nw2 = C_ * C_;
        round_tf32_kernel<<<nx  / 1024, 256>>>(x,    xr,    nx);
        round_tf32_kernel<<<nw1 / 1024, 256>>>(wqkv, wqkvr, nw1);
        round_tf32_kernel<<<nw2 / 1024, 256>>>(wp,   wpr,   nw2);
    }

    // 1) QKV projection (tf32 tensor cores, cp.async pipelined), fused bias
    gemm_tf32_kernel<<<dim3(N1_ / 128, M_ / 128), 128, gemm_smem>>>(
        xr, wqkvr, qb, vb, qkv, N1_, C_, 1);

    // 2) l2norm q/k + per-head scale + transpose to [B,H,L,D]
    norm_kernel<<<(M_ * H_) / 8, 256>>>(qkv, slog, q, k, v);

    // 3) block-diagonal attention, big segments first (output tf32-rounded)
    attn_kernel<<<2560, 256, 131072>>>(q, k, v, slog, att);

    // 4) output projection (tf32 tensor cores, cp.async pipelined) -> d_out
    gemm_tf32_kernel<<<dim3(C_ / 128, M_ / 128), 128, gemm_smem>>>(
        att, wpr, pb, nullptr, out, C_, C_, 0);
}

// round 12
// speedup vs baseline: 1.1103x; 1.0064x over previous
#include <cuda_runtime.h>
#include <cstdint>

// Problem constants
#define B_ 16
#define L_ 680
#define C_ 1024
#define H_ 16
#define D_ 64
#define M_ (B_ * L_)     // 10880
#define N1_ (3 * C_)     // 3072
#define MAXLOG 4.605170185988091f   // ln(100)

// ---------------- scratch (static __device__, no allocations) ----------------
__device__ float g_qkv[(size_t)M_ * N1_];          // GEMM1 output [M, 3C]
__device__ float g_q[(size_t)B_ * H_ * L_ * D_];   // normalized q, [B,H,L,D]
__device__ float g_k[(size_t)B_ * H_ * L_ * D_];
__device__ float g_v[(size_t)B_ * H_ * L_ * D_];
__device__ float g_att[(size_t)M_ * C_];           // attention out (tf32-rounded)
__device__ float g_xr[(size_t)M_ * C_];            // x rounded to tf32
__device__ float g_wqkvr[(size_t)N1_ * C_];        // wqkv rounded to tf32
__device__ float g_wpr[(size_t)C_ * C_];           // wp rounded to tf32

// ---------------- helpers ----------------
__device__ __forceinline__ unsigned f2tf(float x) {
    unsigned r;
    asm("cvt.rna.tf32.f32 %0, %1;" : "=r"(r) : "f"(x));
    return r;
}

__device__ __forceinline__ void mma_tf32(float c[4], const unsigned a[4],
                                         unsigned b0, unsigned b1) {
    asm volatile(
        "mma.sync.aligned.m16n8k8.row.col.f32.tf32.tf32.f32 "
        "{%0,%1,%2,%3}, {%4,%5,%6,%7}, {%8,%9}, {%0,%1,%2,%3};"
        : "+f"(c[0]), "+f"(c[1]), "+f"(c[2]), "+f"(c[3])
        : "r"(a[0]), "r"(a[1]), "r"(a[2]), "r"(a[3]), "r"(b0), "r"(b1));
}

__device__ __forceinline__ void cp16(unsigned* s, const float* g) {
    unsigned sa = (unsigned)__cvta_generic_to_shared(s);
    asm volatile("cp.async.cg.shared.global [%0], [%1], 16;" :: "r"(sa), "l"(g));
}
__device__ __forceinline__ void cp_commit() {
    asm volatile("cp.async.commit_group;");
}
template<int N> __device__ __forceinline__ void cp_wait() {
    asm volatile("cp.async.wait_group %0;" :: "n"(N));
}

// packed f32x2 primitives — operands STAY packed (no movs in hot loops)
typedef unsigned long long u64;
__device__ __forceinline__ void pfma(u64& d, u64 a, u64 b) {
    asm("fma.rn.f32x2 %0, %1, %2, %0;" : "+l"(d) : "l"(a), "l"(b));
}
__device__ __forceinline__ float2 up2(u64 v) {
    float2 r; asm("mov.b64 {%0, %1}, %2;" : "=f"(r.x), "=f"(r.y) : "l"(v)); return r;
}
__device__ __forceinline__ u64 pk2(float x, float y) {
    u64 r; asm("mov.b64 %0, {%1, %2};" : "=l"(r) : "f"(x), "f"(y)); return r;
}

// ---------------- tf32 pre-round (elementwise) ----------------
__global__ __launch_bounds__(256)
void round_tf32_kernel(const float* __restrict__ src, float* __restrict__ dst, int n)
{
    int i = (blockIdx.x * 256 + threadIdx.x) * 4;
    if (i < n) {
        float4 v = *(const float4*)(src + i);
        uint4 r = make_uint4(f2tf(v.x), f2tf(v.y), f2tf(v.z), f2tf(v.w));
        *(uint4*)(dst + i) = r;
    }
}

// ---------------- GEMM: C[m,n] = sum_k A[m,k]*W[n,k] + bias(n) ----------------
// Pre-rounded tf32 inputs; no cvt in hot loop. 256 threads (8 warps),
// CTA tile 128x128, warp tile 64x32 (mt=4, nt=4) -> acc 64 regs, 2 CTA/SM,
// 16 warps/SM to hide LDS/HMMA latency (R10 ran 8 warps/SM, issue=18.8%).
// mode 0: bias = b0p[n]   (proj)
// mode 1: qkv bias: n<1024 -> b0p[n]; n<2048 -> 0; else b1p[n-2048]
#define SROW 36                       // +4 pad: fragment LDS conflict-free
#define STAGEF (2 * 128 * SROW)       // words per stage (A then B)

__global__ __launch_bounds__(256, 2)
void gemm_tf32_kernel(const float* __restrict__ A, const float* __restrict__ W,
                      const float* __restrict__ b0p, const float* __restrict__ b1p,
                      float* __restrict__ Cout, int N, int K, int mode)
{
    extern __shared__ unsigned sm[];

    const int bm = blockIdx.y * 128, bn = blockIdx.x * 128;
    const int tid  = threadIdx.x;
    const int lane = tid & 31, warp = tid >> 5;
    const int wm = (warp & 1) * 64;    // 2 warps along m
    const int wn = (warp >> 1) * 32;   // 4 warps along n
    const int gid = lane >> 2, tig = lane & 3;
    const int lrow = tid >> 3;         // 0..31
    const int lcol = (tid & 7) * 4;    // 0,4,...,28

    float acc[4][4][4];
    #pragma unroll
    for (int mt = 0; mt < 4; mt++)
        #pragma unroll
        for (int nt = 0; nt < 4; nt++)
            #pragma unroll
            for (int r = 0; r < 4; r++) acc[mt][nt][r] = 0.f;

    const float* Ag = A + (size_t)(bm + lrow) * K + lcol;
    const float* Wg = W + (size_t)(bn + lrow) * K + lcol;

    const int NCH = K >> 5;            // 32-wide k chunks

    // prologue: prefetch chunk 0 into stage 0
    {
        unsigned* sA = sm;
        unsigned* sB = sm + 128 * SROW;
        #pragma unroll
        for (int i = 0; i < 4; i++) {
            cp16(&sA[(lrow + i * 32) * SROW + lcol], Ag + (size_t)i * 32 * K);
            cp16(&sB[(lrow + i * 32) * SROW + lcol], Wg + (size_t)i * 32 * K);
        }
        cp_commit();
    }

    for (int it = 0; it < NCH; it++) {
        if (it + 1 < NCH) {
            unsigned* sA = sm + ((it + 1) & 1) * STAGEF;
            unsigned* sB = sA + 128 * SROW;
            const float* Ap = Ag + (size_t)(it + 1) * 32;
            const float* Wp = Wg + (size_t)(it + 1) * 32;
            #pragma unroll
            for (int i = 0; i < 4; i++) {
                cp16(&sA[(lrow + i * 32) * SROW + lcol], Ap + (size_t)i * 32 * K);
                cp16(&sB[(lrow + i * 32) * SROW + lcol], Wp + (size_t)i * 32 * K);
            }
            cp_commit();
            cp_wait<1>();
        } else {
            cp_wait<0>();
        }
        __syncthreads();

        const unsigned* sA = sm + (it & 1) * STAGEF;
        const unsigned* sB = sA + 128 * SROW;

        #pragma unroll
        for (int ks = 0; ks < 32; ks += 8) {
            unsigned a[4][4];
            #pragma unroll
            for (int mt = 0; mt < 4; mt++) {
                int r = wm + mt * 16 + gid;
                a[mt][0] = sA[r * SROW + ks + tig];
                a[mt][1] = sA[(r + 8) * SROW + ks + tig];
                a[mt][2] = sA[r * SROW + ks + tig + 4];
                a[mt][3] = sA[(r + 8) * SROW + ks + tig + 4];
            }
            #pragma unroll
            for (int nt = 0; nt < 4; nt++) {
                int n = wn + nt * 8 + gid;
                unsigned bb0 = sB[n * SROW + ks + tig];
                unsigned bb1 = sB[n * SROW + ks + tig + 4];
                #pragma unroll
                for (int mt = 0; mt < 4; mt++)
                    mma_tf32(acc[mt][nt], a[mt], bb0, bb1);
            }
        }
        __syncthreads();   // stage free for the prefetch two iters ahead
    }

    #pragma unroll
    for (int mt = 0; mt < 4; mt++) {
        #pragma unroll
        for (int nt = 0; nt < 4; nt++) {
            int row = bm + wm + mt * 16 + gid;
            int col = bn + wn + nt * 8 + 2 * tig;
            float bz0, bz1;
            if (mode == 0) {
                bz0 = b0p[col]; bz1 = b0p[col + 1];
            } else {
                if (col < 1024)       { bz0 = b0p[col];        bz1 = b0p[col + 1]; }
                else if (col < 2048)  { bz0 = 0.f;             bz1 = 0.f; }
                else                  { bz0 = b1p[col - 2048]; bz1 = b1p[col - 2047]; }
            }
            *(float2*)&Cout[(size_t)row * N + col] =
                make_float2(acc[mt][nt][0] + bz0, acc[mt][nt][1] + bz1);
            *(float2*)&Cout[(size_t)(row + 8) * N + col] =
                make_float2(acc[mt][nt][2] + bz0, acc[mt][nt][3] + bz1);
        }
    }
}

// ---------------- l2norm + scale + transpose to [B,H,L,D] ----------------
__global__ __launch_bounds__(256)
void norm_kernel(const float* __restrict__ Y, const float* __restrict__ sl,
                 float* __restrict__ Q, float* __restrict__ Ko, float* __restrict__ V)
{
    int w    = blockIdx.x * 8 + (threadIdx.x >> 5);   // one warp per (m,h)
    int lane = threadIdx.x & 31;
    int m = w >> 4, h = w & 15;
    int b = m / L_, l = m % L_;

    const float* row = Y + (size_t)m * N1_ + h * 64 + lane * 2;
    float2 qv = *(const float2*)(row);
    float2 kv = *(const float2*)(row + 1024);
    float2 vv = *(const float2*)(row + 2048);

    float ssq = qv.x * qv.x + qv.y * qv.y;
    float ssk = kv.x * kv.x + kv.y * kv.y;
    #pragma unroll
    for (int o = 16; o; o >>= 1) {
        ssq += __shfl_xor_sync(0xffffffffu, ssq, o);
        ssk += __shfl_xor_sync(0xffffffffu, ssk, o);
    }
    float qs = expf(fminf(sl[h], MAXLOG)) / fmaxf(sqrtf(ssq), 1e-12f);
    float ks = 1.0f / fmaxf(sqrtf(ssk), 1e-12f);

    size_t ob = ((size_t)(b * H_ + h) * L_ + l) * 64 + lane * 2;
    *(float2*)(Q  + ob) = make_float2(qv.x * qs, qv.y * qs);
    *(float2*)(Ko + ob) = make_float2(kv.x * ks, kv.y * ks);
    *(float2*)(V  + ob) = vv;
}

// ---------------- block-diagonal attention ----------------
// seg_hi - (blockIdx.x >> 8) selects segment (256 (b,h) pairs per segment).
// Split into TWO launches so small segments don't pay 128 KB smem:
//   small: segs 0..7 (ln<=100), 128 threads, 51.2 KB  -> 4 CTAs/SM
//   big:   segs 8..9,          256 threads, 128 KB   -> 1 CTA/SM
// thread i = query row i. |q| = scale, |k| = 1 => s <= scale: fixed softmax max.
// Output rounded to tf32 at store (feeds the proj GEMM with no cvt).
__global__ void attn_kernel(const float* __restrict__ Q, const float* __restrict__ Kn,
                            const float* __restrict__ V, const float* __restrict__ sl,
                            float* __restrict__ Att, int seg_hi)
{
    extern __shared__ float smdyn[];
    const int cta = blockIdx.x;
    const int seg = seg_hi - (cta >> 8);     // bigger segs first
    const int hb  = cta & 255;
    const int h = hb & 15, b = hb >> 4;

    const int pn[10]  = {1, 4, 9, 16, 25, 36, 64, 100, 169, 256};
    const int off[10] = {0, 1, 5, 14, 30, 55, 91, 155, 255, 424};
    const int ln = pn[seg], start = off[seg];

    float* Ks = smdyn;
    float* Vs = smdyn + ln * 64;
    const int tid = threadIdx.x;
    const int nthr4 = blockDim.x * 4;
    const size_t base = ((size_t)(b * H_ + h) * L_ + start) * 64;

    for (int idx = tid * 4; idx < ln * 64; idx += nthr4) {
        *(float4*)&Ks[idx] = *(const float4*)&Kn[base + idx];
        *(float4*)&Vs[idx] = *(const float4*)&V[base + idx];
    }
    const float mfix = expf(fminf(sl[h], MAXLOG));
    __syncthreads();

    u64 op[32];
    float lsum = 0.f;
    if (tid < ln) {
        u64 qp[32];
        const u64* qg = (const u64*)(Q + base + (size_t)tid * 64);
        #pragma unroll
        for (int t = 0; t < 32; t++) { qp[t] = qg[t]; op[t] = 0ull; }

        for (int j = 0; j < ln; j++) {
            const u64* kp = (const u64*)(Ks + j * 64);
            u64 s8[8];
            #pragma unroll
            for (int t = 0; t < 8; t++) s8[t] = 0ull;
            #pragma unroll
            for (int t = 0; t < 32; t++) pfma(s8[t & 7], qp[t], kp[t]);

            float tot = 0.f;
            #pragma unroll
            for (int r = 0; r < 8; r++) { float2 f = up2(s8[r]); tot += f.x + f.y; }

            float p = __expf(tot - mfix);
            lsum += p;
            u64 pp = pk2(p, p);

            const u64* vp = (const u64*)(Vs + j * 64);
            #pragma unroll
            for (int t = 0; t < 32; t++) pfma(op[t], pp, vp[t]);
        }
    }
    __syncthreads();              // done reading Ks -> reuse as output stage
    if (tid < ln) {
        float inv = 1.0f / lsum;
        #pragma unroll
        for (int t = 0; t < 32; t++) {
            float2 f = up2(op[t]);
            // round to tf32 here: proj GEMM consumes raw bits with no cvt
            ((unsigned*)Ks)[tid * 64 + 2 * t]     = f2tf(f.x * inv);
            ((unsigned*)Ks)[tid * 64 + 2 * t + 1] = f2tf(f.y * inv);
        }
    }
    __syncthreads();
    const size_t ob = (size_t)(b * L_ + start);
    for (int idx = tid * 4; idx < ln * 64; idx += nthr4) {
        int row = idx >> 6, e = idx & 63;
        *(float4*)&Att[(ob + row) * C_ + h * 64 + e] = *(float4*)&Ks[idx];
    }
}

// ---------------- launch ----------------
extern "C" void kernel_launch(void* const* d_in, const int* in_sizes, int n_in,
                              void* d_out, int out_size)
{
    const float* x    = (const float*)d_in[0];
    // d_in[1] = patch_nums (fixed for this problem; offsets compiled in)
    const float* wqkv = (const float*)d_in[2];
    const float* qb   = (const float*)d_in[3];
    const float* vb   = (const float*)d_in[4];
    const float* slog = (const float*)d_in[5];
    const float* wp   = (const float*)d_in[6];
    const float* pb   = (const float*)d_in[7];
    float* out = (float*)d_out;

    float *qkv, *q, *k, *v, *att, *xr, *wqkvr, *wpr;
    cudaGetSymbolAddress((void**)&qkv,   g_qkv);
    cudaGetSymbolAddress((void**)&q,     g_q);
    cudaGetSymbolAddress((void**)&k,     g_k);
    cudaGetSymbolAddress((void**)&v,     g_v);
    cudaGetSymbolAddress((void**)&att,   g_att);
    cudaGetSymbolAddress((void**)&xr,    g_xr);
    cudaGetSymbolAddress((void**)&wqkvr, g_wqkvr);
    cudaGetSymbolAddress((void**)&wpr,   g_wpr);

    const int gemm_smem = STAGEF * 2 * (int)sizeof(unsigned);   // 73728 B
    const int attn_small_smem = 2 * 100 * 64 * (int)sizeof(float);  // 51200 B
    const int attn_big_smem   = 2 * 256 * 64 * (int)sizeof(float);  // 131072 B
    cudaFuncSetAttribute(gemm_tf32_kernel,
                         cudaFuncAttributeMaxDynamicSharedMemorySize, gemm_smem);
    cudaFuncSetAttribute(attn_kernel,
                         cudaFuncAttributeMaxDynamicSharedMemorySize, attn_big_smem);

    // 0) pre-round GEMM operands to tf32 (GEMM hot loops are cvt-free)
    {
        const int nx = M_ * C_, nw1 = N1_ * C_, nw2 = C_ * C_;
        round_tf32_kernel<<<nx  / 1024, 256>>>(x,    xr,    nx);
        round_tf32_kernel<<<nw1 / 1024, 256>>>(wqkv, wqkvr, nw1);
        round_tf32_kernel<<<nw2 / 1024, 256>>>(wp,   wpr,   nw2);
    }

    // 1) QKV projection (tf32 mma.sync, cp.async pipelined, 16 warps/SM)
    gemm_tf32_kernel<<<dim3(N1_ / 128, M_ / 128), 256, gemm_smem>>>(
        xr, wqkvr, qb, vb, qkv, N1_, C_, 1);

    // 2) l2norm q/k + per-head scale + transpose to [B,H,L,D]
    norm_kernel<<<(M_ * H_) / 8, 256>>>(qkv, slog, q, k, v);

    // 3) block-diagonal attention: big segs (128 KB smem), then small segs
    //    (51.2 KB smem -> 4 CTAs/SM instead of 1)
    attn_kernel<<<512, 256, attn_big_smem>>>(q, k, v, slog, att, 9);
    attn_kernel<<<2048, 128, attn_small_smem>>>(q, k, v, slog, att, 7);

    // 4) output projection (tf32 mma.sync) -> d_out
    gemm_tf32_kernel<<<dim3(C_ / 128, M_ / 128), 256, gemm_smem>>>(
        att, wpr, pb, nullptr, out, C_, C_, 0);
}